// round 6
// baseline (speedup 1.0000x reference)
#include <cuda_runtime.h>

typedef unsigned long long u64;
#define TT 1024
#define NCTA 128

__device__ float    g_h[2][256][256];
__device__ unsigned g_bar;

__global__ void reset_kernel() { if (threadIdx.x == 0) g_bar = 0u; }

__device__ __forceinline__ u64 dup2(float a){ u64 r; asm("mov.b64 %0,{%1,%1};":"=l"(r):"f"(a)); return r; }
__device__ __forceinline__ void fma2(u64& d, u64 a, u64 b){ asm("fma.rn.f32x2 %0,%1,%2,%0;":"+l"(d):"l"(a),"l"(b)); }
__device__ __forceinline__ float lo2(u64 v){ float a,b; asm("mov.b64 {%0,%1},%2;":"=f"(a),"=f"(b):"l"(v)); return a; }
__device__ __forceinline__ float hi2(u64 v){ float a,b; asm("mov.b64 {%0,%1},%2;":"=f"(a),"=f"(b):"l"(v)); return b; }
__device__ __forceinline__ float sigm(float x){ return 1.f/(1.f+__expf(-x)); }

// smem float offsets
#define O_WHH 0        // [256][96]  W_hh^T: [k][g*32+jj]
#define O_WOT 24576    // [256][32]  W_out^T: [k][o]
#define O_WIH 32768    // [64][96]   x-weights: [kk][g*32+jj] (kk<32 obs, kk>=32 y)
#define O_H   38912    // [16][256]
#define O_Y   43008    // [16][32]
#define O_OBS 43520    // [16][32]
#define O_CZ  44032    // [3][16][32] const (bias + z_dyn part)
#define O_BHN 45568    // [32]
#define O_BO  45600    // [32]
#define SMF   45632
#define SMB   (SMF*4)

__global__ void __launch_bounds__(256,1) rnn_kernel(
    const float* __restrict__ init_y, const float* __restrict__ obs_seq,
    const float* __restrict__ z_dyn,  const float* __restrict__ W_ih,
    const float* __restrict__ W_hh,   const float* __restrict__ b_ih,
    const float* __restrict__ b_hh,   const float* __restrict__ W_out,
    const float* __restrict__ b_out,  float* __restrict__ out)
{
    extern __shared__ float s[];
    float* sWHH=s+O_WHH; float* sWOT=s+O_WOT; float* sWIH=s+O_WIH;
    float* sH=s+O_H; float* sY=s+O_Y; float* sOBS=s+O_OBS;
    float* sCZ=s+O_CZ; float* sBHN=s+O_BHN; float* sBO=s+O_BO;

    const int tid=threadIdx.x, jp=tid&15, lb=tid>>4;
    const int fg=blockIdx.x&7, bg=blockIdx.x>>3;
    const int b=bg*16+lb, j0=2*jp;

    // ---- prologue ----
    for(int e=tid;e<24576;e+=256){ int c=e>>8,k=e&255; int g=c>>5,jj=c&31;
        sWHH[k*96+c]=W_hh[(g*256+fg*32+jj)*256+k]; }
    for(int e=tid;e<8192;e+=256){ int o=e>>8,k=e&255; sWOT[k*32+o]=W_out[o*256+k]; }
    for(int e=tid;e<6144;e+=256){ int c=e>>6,col=e&63; int g=c>>5,jj=c&31;
        sWIH[col*96+c]=W_ih[(g*256+fg*32+jj)*96+col]; }
    for(int e=tid;e<1536;e+=256){ int g=e>>9,r2=e&511; int l2=r2>>5,jj=r2&31;
        int row=g*256+fg*32+jj;
        float acc=b_ih[row]+(g<2?b_hh[row]:0.f);
        const float* zp=z_dyn+(size_t)(bg*16+l2)*32;
        #pragma unroll 8
        for(int o=0;o<32;o++) acc=fmaf(W_ih[row*96+64+o],zp[o],acc);
        sCZ[e]=acc; }
    for(int e=tid;e<512;e+=256){ int l2=e>>5,o=e&31;
        sY[e]=init_y[(bg*16+l2)*32+o];
        sOBS[e]=obs_seq[(size_t)(bg*16+l2)*TT*32+o]; }
    for(int e=tid;e<4096;e+=256) sH[e]=0.f;
    if(tid<32){ sBHN[tid]=b_hh[512+fg*32+tid]; sBO[tid]=b_out[tid]; }
    __syncthreads();

    // ---- time loop ----
    for(int t=0;t<TT;t++){
        const float* hb=sH+lb*256;
        const float* wp=sWHH+j0;
        const float* wy=sWOT+j0;
        u64 aR=0,aZ=0,aH=0,aY=0;
        #pragma unroll 4
        for(int k=0;k<256;k++){
            u64 h2=dup2(hb[k]);
            fma2(aR,*(const u64*)(wp+k*96   ),h2);
            fma2(aZ,*(const u64*)(wp+k*96+32),h2);
            fma2(aH,*(const u64*)(wp+k*96+64),h2);
            fma2(aY,*(const u64*)(wy+k*32   ),h2);
        }
        float y0=lo2(aY)+sBO[j0], y1=hi2(aY)+sBO[j0+1];
        if(t>0){
            sY[lb*32+j0]=y0; sY[lb*32+j0+1]=y1;
            if(fg==0){ size_t o=((size_t)b*TT+(t-1))*32+j0; out[o]=y0; out[o+1]=y1; }
        }
        __syncthreads();
        u64 xR=0,xZ=0,xN=0;
        #pragma unroll 4
        for(int kk=0;kk<32;kk++){
            u64 o2=dup2(sOBS[lb*32+kk]);
            const float* w1=sWIH+kk*96+j0;
            fma2(xR,*(const u64*)(w1   ),o2);
            fma2(xZ,*(const u64*)(w1+32),o2);
            fma2(xN,*(const u64*)(w1+64),o2);
            u64 y2=dup2(sY[lb*32+kk]);
            const float* w2=sWIH+(32+kk)*96+j0;
            fma2(xR,*(const u64*)(w2   ),y2);
            fma2(xZ,*(const u64*)(w2+32),y2);
            fma2(xN,*(const u64*)(w2+64),y2);
        }
        const int nb=(t+1)&1;
        #pragma unroll
        for(int f=0;f<2;f++){
            int jj=j0+f;
            float hr=f?hi2(aR):lo2(aR), hz=f?hi2(aZ):lo2(aZ);
            float hn=f?hi2(aH):lo2(aH);
            float xr=f?hi2(xR):lo2(xR), xz=f?hi2(xZ):lo2(xZ), xn=f?hi2(xN):lo2(xN);
            float r=sigm(hr+xr+sCZ[lb*32+jj]);
            float zg=sigm(hz+xz+sCZ[512+lb*32+jj]);
            float n=tanhf(xn+sCZ[1024+lb*32+jj]+r*(hn+sBHN[jj]));
            float hp=hb[fg*32+jj];
            g_h[nb][b][fg*32+jj]=(1.f-zg)*n+zg*hp;
        }
        __syncthreads();
        if(tid==0){
            __threadfence();
            atomicAdd(&g_bar,1u);
            unsigned tgt=(unsigned)(t+1)*NCTA;
            while(*(volatile unsigned*)&g_bar < tgt){}
            __threadfence();
        }
        __syncthreads();
        if(t+1<TT){
            const float4* gp=(const float4*)&g_h[nb][bg*16][0];
            float4* s4=(float4*)sH;
            #pragma unroll
            for(int i=0;i<4;i++) s4[tid+i*256]=__ldcg(gp+tid+i*256);
            #pragma unroll
            for(int i=0;i<2;i++){ int e=tid+i*256; int l2=e>>5,kk=e&31;
                sOBS[e]=obs_seq[((size_t)(bg*16+l2)*TT+(t+1))*32+kk]; }
            __syncthreads();
        }
    }

    // ---- tail: y_{T-1} from h_T (buffer 0) ----
    {
        const float4* gp=(const float4*)&g_h[0][bg*16][0];
        float4* s4=(float4*)sH;
        #pragma unroll
        for(int i=0;i<4;i++) s4[tid+i*256]=__ldcg(gp+tid+i*256);
        __syncthreads();
        const float* hb=sH+lb*256; const float* wy=sWOT+j0;
        u64 aY=0;
        #pragma unroll 4
        for(int k=0;k<256;k++) fma2(aY,*(const u64*)(wy+k*32),dup2(hb[k]));
        if(fg==0){ size_t o=((size_t)b*TT+(TT-1))*32+j0;
            out[o]=lo2(aY)+sBO[j0]; out[o+1]=hi2(aY)+sBO[j0+1]; }
    }
}

extern "C" void kernel_launch(void* const* d_in, const int* in_sizes, int n_in,
                              void* d_out, int out_size)
{
    const float* init_y =(const float*)d_in[0];
    const float* obs_seq=(const float*)d_in[1];
    const float* z_dyn  =(const float*)d_in[2];
    const float* W_ih   =(const float*)d_in[3];
    const float* W_hh   =(const float*)d_in[4];
    const float* b_ih   =(const float*)d_in[5];
    const float* b_hh   =(const float*)d_in[6];
    const float* W_out  =(const float*)d_in[7];
    const float* b_out  =(const float*)d_in[8];
    float* out=(float*)d_out;

    cudaFuncSetAttribute(rnn_kernel, cudaFuncAttributeMaxDynamicSharedMemorySize, SMB);
    reset_kernel<<<1,32>>>();
    rnn_kernel<<<NCTA,256,SMB>>>(init_y,obs_seq,z_dyn,W_ih,W_hh,b_ih,b_hh,W_out,b_out,out);
}

// round 7
// speedup vs baseline: 1.9928x; 1.9928x over previous
#include <cuda_runtime.h>

typedef unsigned long long u64;
#define TT 1024
#define NCTA 128

__device__ float    g_h[2][256][256];
__device__ unsigned g_bar;

__global__ void reset_kernel(){ if(threadIdx.x==0) g_bar=0u; }

__device__ __forceinline__ u64 dup2(float a){ u64 r; asm("mov.b64 %0,{%1,%1};":"=l"(r):"f"(a)); return r; }
__device__ __forceinline__ void fma2(u64& d, u64 a, u64 b){ asm("fma.rn.f32x2 %0,%1,%2,%0;":"+l"(d):"l"(a),"l"(b)); }
__device__ __forceinline__ float lo2(u64 v){ float a,b; asm("mov.b64 {%0,%1},%2;":"=f"(a),"=f"(b):"l"(v)); return a; }
__device__ __forceinline__ float hi2(u64 v){ float a,b; asm("mov.b64 {%0,%1},%2;":"=f"(a),"=f"(b):"l"(v)); return b; }
__device__ __forceinline__ float sigm(float x){ return 1.f/(1.f+__expf(-x)); }

// smem float offsets
#define O_WHH 0        // [256 k][98]  cols 0..95 = (gate r/z/n)*32 + jj, pad 2
#define O_WOT 25088    // [256 k][34]  W_out^T cols 0..31, pad 2
#define O_WIH 33792    // [64 kk][96]  x-weights (kk<32 obs, kk>=32 y)
#define O_SH  39936    // [16 b][256 k]
#define O_P   44032    // partials: [4 ks][64 pos][17 u64] (16 used + pad)
#define O_OBS2 52736   // u64[32 kk][9] packed (b, b+8) pairs
#define O_Y2  53312    // u64[32 o][9]  packed (b, b+8) pairs
#define O_CZ  53888    // [3 g][16 b][32 jj] bias(+b_hh for r,z) + z_dyn part
#define O_BHN 55424    // [32] b_hh n-gate
#define O_BO  55456    // [32] b_out
#define SMF   55488
#define SMB   (SMF*4)

__global__ void __launch_bounds__(256,1) rnn_kernel(
    const float* __restrict__ init_y, const float* __restrict__ obs_seq,
    const float* __restrict__ z_dyn,  const float* __restrict__ W_ih,
    const float* __restrict__ W_hh,   const float* __restrict__ b_ih,
    const float* __restrict__ b_hh,   const float* __restrict__ W_out,
    const float* __restrict__ b_out,  float* __restrict__ out)
{
    extern __shared__ float s[];
    const int tid=threadIdx.x;
    // phase-1 mapping
    const int jp=tid&15, bq=(tid>>4)&3, ks=tid>>6;
    // phase-3/4/5 mapping
    const int jj=tid&31, bh=tid>>5;              // batches bh and bh+8
    const int fg=blockIdx.x&7, bg=blockIdx.x>>3;

    // ---------------- prologue ----------------
    for(int e=tid;e<24576;e+=256){ int c=e>>8,k=e&255; int g=c>>5,jl=c&31;
        s[O_WHH+k*98+c]=W_hh[(g*256+fg*32+jl)*256+k]; }
    for(int e=tid;e<8192;e+=256){ int o=e>>8,k=e&255; s[O_WOT+k*34+o]=W_out[o*256+k]; }
    for(int e=tid;e<6144;e+=256){ int c=e>>6,col=e&63; int g=c>>5,jl=c&31;
        s[O_WIH+col*96+c]=W_ih[(g*256+fg*32+jl)*96+col]; }
    for(int e=tid;e<1536;e+=256){ int g=e>>9,rem=e&511; int b=rem>>5,jl=rem&31;
        int row=g*256+fg*32+jl;
        float acc=b_ih[row]+(g<2?b_hh[row]:0.f);
        const float* zp=z_dyn+(size_t)(bg*16+b)*32;
        #pragma unroll 8
        for(int o=0;o<32;o++) acc=fmaf(W_ih[row*96+64+o],zp[o],acc);
        s[O_CZ+e]=acc; }
    for(int e=tid;e<512;e+=256){ int b=e>>5,kk=e&31;
        s[O_OBS2+(kk*9+(b&7))*2+(b>>3)]=obs_seq[((size_t)(bg*16+b)*TT)*32+kk];
        s[O_Y2  +(kk*9+(b&7))*2+(b>>3)]=init_y[(bg*16+b)*32+kk]; }
    for(int e=tid;e<4096;e+=256) s[O_SH+e]=0.f;
    if(tid<32){ s[O_BHN+tid]=b_hh[512+fg*32+tid]; s[O_BO+tid]=b_out[tid]; }
    __syncthreads();

    const int pos0=(jj>>1)+16*(bh>>2), pos1=pos0+32, hf=jj&1, bm=(bh&3);

    // ---------------- time loop ----------------
    for(int t=0;t<TT;t++){
        if(t>0){
            // stage h_t from global (written by all fg CTAs) + obs_t
            const int cur=t&1;
            const float4* gp=(const float4*)&g_h[cur][bg*16][0];
            float4* s4=(float4*)(s+O_SH);
            #pragma unroll
            for(int i=0;i<4;i++) s4[tid+i*256]=__ldcg(gp+tid+i*256);
            #pragma unroll
            for(int i=0;i<2;i++){ int e=tid+i*256; int b=e>>5,kk=e&31;
                s[O_OBS2+(kk*9+(b&7))*2+(b>>3)]=obs_seq[((size_t)(bg*16+b)*TT+t)*32+kk]; }
            __syncthreads();
        }

        // ---- P1: h-loop, 4-batch register blocking, gates R,Z,HN,Y ----
        u64 A[16];
        #pragma unroll
        for(int i=0;i<16;i++) A[i]=0ull;
        {
            const float* wk=s+O_WHH+(ks*64)*98+2*jp;
            const float* wy=s+O_WOT+(ks*64)*34+2*jp;
            const float* hb=s+O_SH+(bq*4)*256+ks*64;
            #pragma unroll 4
            for(int kk=0;kk<64;kk++){
                u64 wR=*(const u64*)(wk), wZ=*(const u64*)(wk+32);
                u64 wN=*(const u64*)(wk+64), wY=*(const u64*)(wy);
                #pragma unroll
                for(int i=0;i<4;i++){
                    u64 hd=dup2(hb[i*256+kk]);
                    fma2(A[i],wR,hd); fma2(A[4+i],wZ,hd);
                    fma2(A[8+i],wN,hd); fma2(A[12+i],wY,hd);
                }
                wk+=98; wy+=34;
            }
        }
        // ---- P2: store partials ----
        {
            float* pp=s+O_P+ks*2176+(jp+16*bq)*34;
            #pragma unroll
            for(int i=0;i<16;i++) *(u64*)(pp+2*i)=A[i];
        }
        __syncthreads();

        // ---- P3: reduce gates (regs) + y feedback/out ----
        float rs0=0,zs0=0,ns0=0,rs1=0,zs1=0,ns1=0;
        {
            #pragma unroll
            for(int k4=0;k4<4;k4++){
                const float* p0=s+O_P+k4*2176+pos0*34+hf;
                const float* p1=s+O_P+k4*2176+pos1*34+hf;
                rs0+=p0[bm*2]; zs0+=p0[(4+bm)*2]; ns0+=p0[(8+bm)*2];
                rs1+=p1[bm*2]; zs1+=p1[(4+bm)*2]; ns1+=p1[(8+bm)*2];
            }
            if(t>0){
                float y0=s[O_BO+jj], y1=y0;
                #pragma unroll
                for(int k4=0;k4<4;k4++){
                    y0+=s[O_P+k4*2176+pos0*34+(12+bm)*2+hf];
                    y1+=s[O_P+k4*2176+pos1*34+(12+bm)*2+hf];
                }
                u64 yp; asm("mov.b64 %0,{%1,%2};":"=l"(yp):"f"(y0),"f"(y1));
                *(u64*)(s+O_Y2+(jj*9+bh)*2)=yp;
                if(fg==0){
                    out[((size_t)(bg*16+bh  )*TT+(t-1))*32+jj]=y0;
                    out[((size_t)(bg*16+bh+8)*TT+(t-1))*32+jj]=y1;
                }
            }
        }
        __syncthreads();

        // ---- P4: x-loop (obs + y feedback), batches packed in f32x2 ----
        u64 XR=0,XZ=0,XN=0;
        {
            const float* wx=s+O_WIH+jj;
            const u64* xo=(const u64*)(s+O_OBS2)+bh;
            const u64* xy=(const u64*)(s+O_Y2)+bh;
            #pragma unroll 4
            for(int kk=0;kk<32;kk++){
                u64 x2=xo[kk*9];
                const float* w=wx+kk*96;
                fma2(XR,dup2(w[0]),x2); fma2(XZ,dup2(w[32]),x2); fma2(XN,dup2(w[64]),x2);
            }
            #pragma unroll 4
            for(int kk=0;kk<32;kk++){
                u64 y2=xy[kk*9];
                const float* w=wx+(32+kk)*96;
                fma2(XR,dup2(w[0]),y2); fma2(XZ,dup2(w[32]),y2); fma2(XN,dup2(w[64]),y2);
            }
        }
        // ---- P5: activations + h update ----
        {
            const int nb=(t+1)&1;
            float r0=sigm(rs0+lo2(XR)+s[O_CZ+bh*32+jj]);
            float z0=sigm(zs0+lo2(XZ)+s[O_CZ+512+bh*32+jj]);
            float n0=tanhf(lo2(XN)+s[O_CZ+1024+bh*32+jj]+r0*(ns0+s[O_BHN+jj]));
            float hp0=s[O_SH+bh*256+fg*32+jj];
            g_h[nb][bg*16+bh][fg*32+jj]=(1.f-z0)*n0+z0*hp0;
            float r1=sigm(rs1+hi2(XR)+s[O_CZ+(bh+8)*32+jj]);
            float z1=sigm(zs1+hi2(XZ)+s[O_CZ+512+(bh+8)*32+jj]);
            float n1=tanhf(hi2(XN)+s[O_CZ+1024+(bh+8)*32+jj]+r1*(ns1+s[O_BHN+jj]));
            float hp1=s[O_SH+(bh+8)*256+fg*32+jj];
            g_h[nb][bg*16+bh+8][fg*32+jj]=(1.f-z1)*n1+z1*hp1;
        }
        // ---- P6: global barrier (release/acquire) ----
        __syncthreads();
        if(tid==0){
            unsigned tgt=(unsigned)(t+1)*NCTA, v;
            asm volatile("red.release.gpu.global.add.u32 [%0],1;"::"l"(&g_bar):"memory");
            do{ asm volatile("ld.acquire.gpu.global.u32 %0,[%1];":"=r"(v):"l"(&g_bar):"memory"); }while(v<tgt);
        }
        __syncthreads();
    }

    // ---------------- tail: y_{T-1} from h_T (buffer 0) ----------------
    {
        const float4* gp=(const float4*)&g_h[0][bg*16][0];
        float4* s4=(float4*)(s+O_SH);
        #pragma unroll
        for(int i=0;i<4;i++) s4[tid+i*256]=__ldcg(gp+tid+i*256);
        __syncthreads();
        u64 AY[4]={0,0,0,0};
        const float* wy=s+O_WOT+(ks*64)*34+2*jp;
        const float* hb=s+O_SH+(bq*4)*256+ks*64;
        #pragma unroll 4
        for(int kk=0;kk<64;kk++){
            u64 wY=*(const u64*)(wy);
            #pragma unroll
            for(int i=0;i<4;i++) fma2(AY[i],wY,dup2(hb[i*256+kk]));
            wy+=34;
        }
        float* pp=s+O_P+ks*2176+(jp+16*bq)*34;
        #pragma unroll
        for(int i=0;i<4;i++) *(u64*)(pp+2*(12+i))=AY[i];
        __syncthreads();
        if(fg==0){
            float y0=s[O_BO+jj], y1=y0;
            #pragma unroll
            for(int k4=0;k4<4;k4++){
                y0+=s[O_P+k4*2176+pos0*34+(12+bm)*2+hf];
                y1+=s[O_P+k4*2176+pos1*34+(12+bm)*2+hf];
            }
            out[((size_t)(bg*16+bh  )*TT+(TT-1))*32+jj]=y0;
            out[((size_t)(bg*16+bh+8)*TT+(TT-1))*32+jj]=y1;
        }
    }
}

extern "C" void kernel_launch(void* const* d_in, const int* in_sizes, int n_in,
                              void* d_out, int out_size)
{
    const float* init_y =(const float*)d_in[0];
    const float* obs_seq=(const float*)d_in[1];
    const float* z_dyn  =(const float*)d_in[2];
    const float* W_ih   =(const float*)d_in[3];
    const float* W_hh   =(const float*)d_in[4];
    const float* b_ih   =(const float*)d_in[5];
    const float* b_hh   =(const float*)d_in[6];
    const float* W_out  =(const float*)d_in[7];
    const float* b_out  =(const float*)d_in[8];
    float* out=(float*)d_out;

    cudaFuncSetAttribute(rnn_kernel, cudaFuncAttributeMaxDynamicSharedMemorySize, SMB);
    reset_kernel<<<1,32>>>();
    rnn_kernel<<<NCTA,256,SMB>>>(init_y,obs_seq,z_dyn,W_ih,W_hh,b_ih,b_hh,W_out,b_out,out);
}